// round 15
// baseline (speedup 1.0000x reference)
#include <cuda_runtime.h>
#include <math.h>

// Problem constants (fixed by the reference)
#define NN 8192
#define KK 16
#define GAMMA_MIN 0.9f
#define GAMMA_MAX 0.9995f

#define ROWS_PER_BLOCK 4       // R15: 512thr x 4 rows keeps the proven 32KB/block
#define THREADS 512            //      quanta but doubles per-row contiguity to 8KB
#define N4 (NN / 4)            // 2048 float4 per row

// ---------------------------------------------------------------------------
// R15 experiment: block-shape sweep (only axis never tested).
// Identical mechanics to the proven 42.0us config: __stcs float4 stores,
// 32KB stores per block, x-fastest grid, parallel-staged Phase A.
// Changed: 256thr/8rows -> 512thr/4rows. Each row segment is now 8KB
// contiguous (vs 4KB), 4096 blocks, 4 blocks/SM = 2048 thr (full occupancy).
//   Phase A1: gammas computed by 16 PARALLEL threads, staged via smem.
//   Phase A2: per-row nonzero compaction of c[k] = gamma_k * v[k][n]
//             (general: handles any nnz in [0,16]).
//   Phase B:  W[n][m] = sum_i c_i * u[k_i][m]; register-cached u vector,
//             128-bit evict-first streaming stores.
// ---------------------------------------------------------------------------
__global__ __launch_bounds__(THREADS)
void wslow_fused_kernel(const float* __restrict__ eta,
                        const float* __restrict__ v,
                        const float* __restrict__ u,
                        float* __restrict__ out) {
    const int m4 = blockIdx.x * THREADS + threadIdx.x;   // float4 column index
    const int n0 = blockIdx.y * ROWS_PER_BLOCK;          // first row of tile
    const int t  = threadIdx.x;

    __shared__ float s_gam[KK];
    __shared__ int   s_nnz[ROWS_PER_BLOCK];
    __shared__ int   s_k[ROWS_PER_BLOCK][KK];
    __shared__ float s_c[ROWS_PER_BLOCK][KK];

    // --- Phase A1: gammas (16 parallel threads) ---
    if (t < KK) {
        float e = eta[t];
        float s = 1.0f / (1.0f + expf(-e));
        s_gam[t] = GAMMA_MIN + (GAMMA_MAX - GAMMA_MIN) * s;
    }
    __syncthreads();

    // --- Phase A2: per-row compaction (one thread per row) ---
    if (t < ROWS_PER_BLOCK) {
        const int n = n0 + t;
        int cnt = 0;
#pragma unroll
        for (int k = 0; k < KK; k++) {
            float c = s_gam[k] * v[k * NN + n];
            if (c != 0.0f) {
                s_k[t][cnt] = k;
                s_c[t][cnt] = c;
                cnt++;
            }
        }
        s_nnz[t] = cnt;
    }
    __syncthreads();

    // --- Phase B: streamed outer-product accumulation ---
    const float4* __restrict__ u4 = reinterpret_cast<const float4*>(u);
    float4* __restrict__ o4 = reinterpret_cast<float4*>(out) + (size_t)n0 * N4 + m4;

    int    kprev = -1;
    float4 uv    = make_float4(0.f, 0.f, 0.f, 0.f);

#pragma unroll
    for (int r = 0; r < ROWS_PER_BLOCK; r++) {
        float4 acc = make_float4(0.f, 0.f, 0.f, 0.f);
        const int nn = s_nnz[r];
        for (int i = 0; i < nn; i++) {
            const int k = s_k[r][i];
            if (k != kprev) {                 // block-uniform branch
                uv = __ldg(&u4[k * N4 + m4]); // L1/L2-resident
                kprev = k;
            }
            const float c = s_c[r][i];
            acc.x = fmaf(c, uv.x, acc.x);
            acc.y = fmaf(c, uv.y, acc.y);
            acc.z = fmaf(c, uv.z, acc.z);
            acc.w = fmaf(c, uv.w, acc.w);
        }
        __stcs(o4, acc);                      // streaming 128-bit store (proven best)
        o4 += N4;
    }
}

// ---------------------------------------------------------------------------
extern "C" void kernel_launch(void* const* d_in, const int* in_sizes, int n_in,
                              void* d_out, int out_size) {
    const float* eta = (const float*)d_in[0];   // [16]
    const float* v   = (const float*)d_in[1];   // [16, 8192]
    const float* u   = (const float*)d_in[2];   // [16, 8192]
    float* out = (float*)d_out;                 // [8192, 8192] fp32

    dim3 grid(N4 / THREADS, NN / ROWS_PER_BLOCK);   // (4, 2048) = 8192... 
    wslow_fused_kernel<<<grid, THREADS>>>(eta, v, u, out);
}

// round 16
// speedup vs baseline: 1.0887x; 1.0887x over previous
#include <cuda_runtime.h>
#include <math.h>

// Problem constants (fixed by the reference)
#define NN 8192
#define KK 16
#define GAMMA_MIN 0.9f
#define GAMMA_MAX 0.9995f

#define ROWS_PER_BLOCK 8       // proven optimum (32/16/8/4 = 43.5/43.1/42.0/44.9 us)
#define THREADS 256            // proven optimum (512thr/4rows = 45.2 us)
#define N4 (NN / 4)            // 2048 float4 per row

// ---------------------------------------------------------------------------
// FINAL (R8 config; measured 42.0 / 42.3 / 42.2 / 42.3 us across runs).
// Fused single kernel, __stcs float4 stores, 256 threads,
// 8 rows x 32KB stores per block, 8192 blocks (x-fastest grid), 8 blocks/SM.
//
// Full design-space map (wall-time evidence, 15 rounds):
//   fusion      : 2-kernel 53.1 | fused 43.5+
//   store policy: cs 42.0 | wb 47.0 | wt 47.1 | TMA bulk 47.8
//   store width : 128b 42.0 | 256b 47.2 (occupancy collapse)
//   ROWS quanta : 32/16/8/4 = 43.5/43.1/42.0/44.9
//   block shape : 256x8 42.0 | 512x4 45.2
//   grid order  : x-fastest 42.0 | y-fastest 47.6
//   Phase A     : parallel-staged 42.0 | inline-serial 57.6
// 268 MB / 42 us = 6.4 TB/s write stream (~80% of 8 TB/s spec); all SM pipes
// < 48% -> HBM write-path floor. Local optimum in every tested direction.
//
//   Phase A1: gammas computed by 16 PARALLEL threads, staged via smem.
//   Phase A2: per-row nonzero compaction of c[k] = gamma_k * v[k][n]
//             (general: handles any nnz in [0,16]).
//   Phase B:  W[n][m] = sum_i c_i * u[k_i][m]; register-cached u vector,
//             128-bit evict-first streaming stores.
// ---------------------------------------------------------------------------
__global__ __launch_bounds__(THREADS)
void wslow_fused_kernel(const float* __restrict__ eta,
                        const float* __restrict__ v,
                        const float* __restrict__ u,
                        float* __restrict__ out) {
    const int m4 = blockIdx.x * THREADS + threadIdx.x;   // float4 column index
    const int n0 = blockIdx.y * ROWS_PER_BLOCK;          // first row of tile
    const int t  = threadIdx.x;

    __shared__ float s_gam[KK];
    __shared__ int   s_nnz[ROWS_PER_BLOCK];
    __shared__ int   s_k[ROWS_PER_BLOCK][KK];
    __shared__ float s_c[ROWS_PER_BLOCK][KK];

    // --- Phase A1: gammas (16 parallel threads) ---
    if (t < KK) {
        float e = eta[t];
        float s = 1.0f / (1.0f + expf(-e));
        s_gam[t] = GAMMA_MIN + (GAMMA_MAX - GAMMA_MIN) * s;
    }
    __syncthreads();

    // --- Phase A2: per-row compaction (one thread per row) ---
    if (t < ROWS_PER_BLOCK) {
        const int n = n0 + t;
        int cnt = 0;
#pragma unroll
        for (int k = 0; k < KK; k++) {
            float c = s_gam[k] * v[k * NN + n];
            if (c != 0.0f) {
                s_k[t][cnt] = k;
                s_c[t][cnt] = c;
                cnt++;
            }
        }
        s_nnz[t] = cnt;
    }
    __syncthreads();

    // --- Phase B: streamed outer-product accumulation ---
    const float4* __restrict__ u4 = reinterpret_cast<const float4*>(u);
    float4* __restrict__ o4 = reinterpret_cast<float4*>(out) + (size_t)n0 * N4 + m4;

    int    kprev = -1;
    float4 uv    = make_float4(0.f, 0.f, 0.f, 0.f);

#pragma unroll
    for (int r = 0; r < ROWS_PER_BLOCK; r++) {
        float4 acc = make_float4(0.f, 0.f, 0.f, 0.f);
        const int nn = s_nnz[r];
        for (int i = 0; i < nn; i++) {
            const int k = s_k[r][i];
            if (k != kprev) {                 // block-uniform branch
                uv = __ldg(&u4[k * N4 + m4]); // L1/L2-resident
                kprev = k;
            }
            const float c = s_c[r][i];
            acc.x = fmaf(c, uv.x, acc.x);
            acc.y = fmaf(c, uv.y, acc.y);
            acc.z = fmaf(c, uv.z, acc.z);
            acc.w = fmaf(c, uv.w, acc.w);
        }
        __stcs(o4, acc);                      // streaming 128-bit store (proven best)
        o4 += N4;
    }
}

// ---------------------------------------------------------------------------
extern "C" void kernel_launch(void* const* d_in, const int* in_sizes, int n_in,
                              void* d_out, int out_size) {
    const float* eta = (const float*)d_in[0];   // [16]
    const float* v   = (const float*)d_in[1];   // [16, 8192]
    const float* u   = (const float*)d_in[2];   // [16, 8192]
    float* out = (float*)d_out;                 // [8192, 8192] fp32

    dim3 grid(N4 / THREADS, NN / ROWS_PER_BLOCK);   // (8, 1024) = 8192 blocks
    wslow_fused_kernel<<<grid, THREADS>>>(eta, v, u, out);
}